// round 2
// baseline (speedup 1.0000x reference)
#include <cuda_runtime.h>
#include <math.h>

// Problem constants
#define NMAT   4096
#define MM     4095               // N-1 (modulus of the tournament schedule)
#define HALF   2048               // N/2 pairs per round
#define RNDS   4095               // rounds
#define NPAIRS (RNDS * HALF)      // 8,386,560
#define CPT    7                  // columns per CTA (odd stride -> conflict-free LDS)
#define THREADS 512

// Pre-gathered (cos, sin) per (round, pair), laid out exactly in round-major
// order so the main kernel streams it sequentially (L2-broadcast across CTAs).
__device__ float2 g_csn[NPAIRS];   // 67 MB static scratch (allowed)

__global__ void precompute_csn(const float* __restrict__ thetas,
                               const int*   __restrict__ round_theta) {
    int x = blockIdx.x * blockDim.x + threadIdx.x;
    if (x < NPAIRS) {
        float th = thetas[round_theta[x]];
        float s, c;
        sincosf(th, &s, &c);       // accurate version: avoid systematic norm drift
        g_csn[x] = make_float2(c, s);
    }
}

// Each CTA owns CPT consecutive columns of U, resident in shared memory
// (4096 rows x 7 cols fp32 = 114,688 B). It sweeps all 4095 rounds locally.
// Pairs within a round are disjoint -> only one __syncthreads per round.
__global__ void __launch_bounds__(THREADS)
rotmat_kernel(float* __restrict__ out) {
    extern __shared__ float sm[];           // [NMAT * CPT], row stride 7 (odd)
    const int c0   = blockIdx.x * CPT;
    const int cols = (NMAT - c0 < CPT) ? (NMAT - c0) : CPT;
    const int tid  = threadIdx.x;

    // Init identity slab
    for (int i = tid; i < NMAT * CPT; i += THREADS) sm[i] = 0.0f;
    __syncthreads();
    if (tid < cols) sm[(c0 + tid) * CPT + tid] = 1.0f;
    __syncthreads();

    for (int r = 0; r < RNDS; ++r) {
        const float2* __restrict__ csn = g_csn + (size_t)r * HALF;
        #pragma unroll 1
        for (int p = tid; p < HALF; p += THREADS) {
            int a, b;
            if (p == 0) {
                a = r;       // i = r % MM (r < MM), j = MM -> already ordered
                b = MM;
            } else {
                a = r + p; if (a >= MM) a -= MM;
                b = r - p; if (b < 0)   b += MM;
                if (a > b) { int t = a; a = b; b = t; }   // i = min, j = max
            }
            const float2 cs = csn[p];
            const float c = cs.x, s = cs.y;
            float* __restrict__ pa = sm + a * CPT;
            float* __restrict__ pb = sm + b * CPT;
            #pragma unroll
            for (int cc = 0; cc < CPT; ++cc) {
                const float ui = pa[cc];
                const float uj = pb[cc];
                pa[cc] = fmaf(c, ui, -s * uj);   // U[i] = c*Ui - s*Uj
                pb[cc] = fmaf(s, ui,  c * uj);   // U[j] = s*Ui + c*Uj
            }
        }
        __syncthreads();
    }

    // Write back: row-major U[row][col]
    for (int row = tid; row < NMAT; row += THREADS) {
        const float* __restrict__ src = sm + row * CPT;
        float* __restrict__ dst = out + (size_t)row * NMAT + c0;
        #pragma unroll
        for (int cc = 0; cc < CPT; ++cc) {
            if (cc < cols) dst[cc] = src[cc];
        }
    }
}

extern "C" void kernel_launch(void* const* d_in, const int* in_sizes, int n_in,
                              void* d_out, int out_size) {
    const float* thetas      = (const float*)d_in[0];
    // d_in[1] = round_i, d_in[2] = round_j (recomputed on the fly in-kernel)
    const int*   round_theta = (const int*)d_in[3];
    float*       out         = (float*)d_out;

    (void)in_sizes; (void)n_in; (void)out_size;

    cudaFuncSetAttribute(rotmat_kernel,
                         cudaFuncAttributeMaxDynamicSharedMemorySize,
                         NMAT * CPT * (int)sizeof(float));

    precompute_csn<<<(NPAIRS + 255) / 256, 256>>>(thetas, round_theta);

    const int nblocks = (NMAT + CPT - 1) / CPT;   // 586
    rotmat_kernel<<<nblocks, THREADS, NMAT * CPT * sizeof(float)>>>(out);
}

// round 3
// speedup vs baseline: 1.0206x; 1.0206x over previous
#include <cuda_runtime.h>
#include <math.h>

// Problem constants
#define NMAT   4096
#define MM     4095               // N-1 (modulus of the tournament schedule)
#define HALF   2048               // N/2 pairs per round
#define RNDS   4095               // rounds
#define NPAIRS (RNDS * HALF)      // 8,386,560
#define CPT    7                  // columns per CTA (odd stride -> conflict-free LDS)
#define THREADS 512

// Pre-gathered (cos, sin) per (round, pair), laid out exactly in round-major
// order so the main kernel streams it sequentially (L2-broadcast across CTAs).
__device__ float2 g_csn[NPAIRS];   // 67 MB static scratch (allowed)

__global__ void precompute_csn(const float* __restrict__ thetas,
                               const int*   __restrict__ round_theta) {
    int x = blockIdx.x * blockDim.x + threadIdx.x;
    if (x < NPAIRS) {
        float th = thetas[round_theta[x]];
        float s, c;
        sincosf(th, &s, &c);       // accurate version: avoid systematic norm drift
        g_csn[x] = make_float2(c, s);
    }
}

// Each CTA owns CPT consecutive columns of U, resident in shared memory
// (4096 rows x 7 cols fp32 = 114,688 B). It sweeps all 4095 rounds locally.
// Pairs within a round are disjoint -> only one __syncthreads per round.
__global__ void __launch_bounds__(THREADS)
rotmat_kernel(float* __restrict__ out) {
    extern __shared__ float sm[];           // [NMAT * CPT], row stride 7 (odd)
    const int c0   = blockIdx.x * CPT;
    const int cols = (NMAT - c0 < CPT) ? (NMAT - c0) : CPT;
    const int tid  = threadIdx.x;

    // Init identity slab
    for (int i = tid; i < NMAT * CPT; i += THREADS) sm[i] = 0.0f;
    __syncthreads();
    if (tid < cols) sm[(c0 + tid) * CPT + tid] = 1.0f;
    __syncthreads();

    for (int r = 0; r < RNDS; ++r) {
        const float2* __restrict__ csn = g_csn + (size_t)r * HALF;
        #pragma unroll 1
        for (int p = tid; p < HALF; p += THREADS) {
            int a, b;
            if (p == 0) {
                a = r;       // i = r % MM (r < MM), j = MM -> already ordered
                b = MM;
            } else {
                a = r + p; if (a >= MM) a -= MM;
                b = r - p; if (b < 0)   b += MM;
                if (a > b) { int t = a; a = b; b = t; }   // i = min, j = max
            }
            const float2 cs = csn[p];
            const float c = cs.x, s = cs.y;
            float* __restrict__ pa = sm + a * CPT;
            float* __restrict__ pb = sm + b * CPT;
            #pragma unroll
            for (int cc = 0; cc < CPT; ++cc) {
                const float ui = pa[cc];
                const float uj = pb[cc];
                pa[cc] = fmaf(c, ui, -s * uj);   // U[i] = c*Ui - s*Uj
                pb[cc] = fmaf(s, ui,  c * uj);   // U[j] = s*Ui + c*Uj
            }
        }
        __syncthreads();
    }

    // Write back: row-major U[row][col]
    for (int row = tid; row < NMAT; row += THREADS) {
        const float* __restrict__ src = sm + row * CPT;
        float* __restrict__ dst = out + (size_t)row * NMAT + c0;
        #pragma unroll
        for (int cc = 0; cc < CPT; ++cc) {
            if (cc < cols) dst[cc] = src[cc];
        }
    }
}

extern "C" void kernel_launch(void* const* d_in, const int* in_sizes, int n_in,
                              void* d_out, int out_size) {
    const float* thetas      = (const float*)d_in[0];
    // d_in[1] = round_i, d_in[2] = round_j (recomputed on the fly in-kernel)
    const int*   round_theta = (const int*)d_in[3];
    float*       out         = (float*)d_out;

    (void)in_sizes; (void)n_in; (void)out_size;

    cudaFuncSetAttribute(rotmat_kernel,
                         cudaFuncAttributeMaxDynamicSharedMemorySize,
                         NMAT * CPT * (int)sizeof(float));

    precompute_csn<<<(NPAIRS + 255) / 256, 256>>>(thetas, round_theta);

    const int nblocks = (NMAT + CPT - 1) / CPT;   // 586
    rotmat_kernel<<<nblocks, THREADS, NMAT * CPT * sizeof(float)>>>(out);
}

// round 8
// speedup vs baseline: 1.2035x; 1.1792x over previous
#include <cuda_runtime.h>
#include <math.h>

#define MM    4095
#define NT    315            // tiles (13*315 = 4095)
#define T     13
#define NTILE 157            // off-diag tiles per anti-diagonal
#define CPT   7
#define THREADS 576
#define SLOTS 82             // 82*7 = 574 <= 576; ceil(157/82)=2
#define NPAIRS (4095LL*2048LL)

// Off-diagonal rotations: [sigma][cell 0..168][m 1..157], cell in anti-diag order
__device__ float2 g_csF[(size_t)NT * 169 * NTILE];   // ~67 MB
// Diagonal-tile rotations, dense [A][ia*13+ib] (specials at ia==ib)
__device__ float2 g_csD[NT * 169];

__global__ void precompute(const float* __restrict__ thetas,
                           const int*   __restrict__ round_theta) {
    long long idx = blockIdx.x * (long long)blockDim.x + threadIdx.x;
    if (idx >= NPAIRS) return;
    int r = (int)(idx >> 11), k = (int)(idx & 2047);
    float th = thetas[round_theta[idx]];
    float s, c; sincosf(th, &s, &c);
    if (k == 0) {                       // special: rows (r, 4095), i = r
        int u = (int)((2048LL * r) % MM);
        int A = u / T, ia = u - A * T;
        g_csD[A * 169 + ia * T + ia] = make_float2(c, s);
    } else {
        int a0 = r + k; if (a0 >= MM) a0 -= MM;
        int b0 = r - k; if (b0 < 0)   b0 += MM;
        int i = min(a0, b0), j = max(a0, b0);
        int ui = (int)((2048LL * i) % MM);
        int uj = (int)((2048LL * j) % MM);
        int ua = min(ui, uj), ub = max(ui, uj);
        float sg = (ua == ui) ? s : -s;     // orient for (x=ua-row, y=ub-row)
        int A = ua / T, ia = ua - A * T;
        int B = ub / T, ib = ub - B * T;
        if (A == B) {
            g_csD[A * 169 + ia * T + ib] = make_float2(c, sg);
        } else {
            int d   = ia + ib;
            int sig = A + B; if (sig >= NT) sig -= NT;
            int aD  = (sig * 158) % NT;     // 2*aD == sig (mod 315)
            int mm  = A - aD; if (mm < 0) mm += NT;
            int m   = (mm <= NTILE) ? mm : NT - mm;
            int cell = (d < T) ? d * (d + 1) / 2 + ia
                               : 91 + (d - T) * (38 - d) / 2 + ia - (d - 12);
            g_csF[((size_t)sig * 169 + cell) * NTILE + (m - 1)] = make_float2(c, sg);
        }
    }
}

__device__ __forceinline__ void rot(float& x, float& y, float2 cs) {
    float xo = x, yo = y;
    x = fmaf(cs.x, xo, -(cs.y * yo));
    y = fmaf(cs.y, xo,  (cs.x * yo));
}

__device__ __forceinline__ void tileAB(int sigma, int m, int& A, int& B) {
    int aD = (sigma * 158) % NT;
    int a = aD + m; if (a >= NT) a -= NT;
    int b = aD - m; if (b < 0)   b += NT;
    A = min(a, b); B = max(a, b);
}

// Visit off-diag tile (A,B): apply cells with inner anti-diag d in [D0,D1].
template<int D0, int D1>
__device__ __forceinline__ void visit(float* __restrict__ sm, int A, int B,
                                      int cc, const float2* __restrict__ cs) {
    float ra[T], rb[T];
    float* pa = sm + 91 * A + cc;   // 91 = 13 rows * stride 7
    float* pb = sm + 91 * B + cc;
    #pragma unroll
    for (int q = 0; q < T; ++q) { ra[q] = pa[q * CPT]; rb[q] = pb[q * CPT]; }
    #pragma unroll
    for (int d = D0; d <= D1; ++d) {
        const int plo = (d < T) ? 0 : d - 12;
        const int phi = (d < T) ? d : 12;
        #pragma unroll
        for (int p = plo; p <= phi; ++p) {
            const int cell = (d < T) ? d * (d + 1) / 2 + p
                                     : 91 + (d - T) * (38 - d) / 2 + p - (d - 12);
            rot(ra[p], rb[d - p], cs[cell * NTILE]);
        }
    }
    #pragma unroll
    for (int q = 0; q < T; ++q) { pa[q * CPT] = ra[q]; pb[q * CPT] = rb[q]; }
}

// Diagonal phase for step s: early half of diag tile aE (2aE==s), late half of
// diag tile aL (2aL==s-1), specials chained through row 4095 in round order.
__device__ __forceinline__ void visit_diag(float* __restrict__ sm,
                                           int aE, int aL, int cc) {
    const float2* __restrict__ csE = g_csD + aE * 169;
    const float2* __restrict__ csL = g_csD + aL * 169;
    float re[T], rl[T];
    float* pe = sm + 91 * aE + cc;
    float* pl = sm + 91 * aL + cc;
    float sp = sm[MM * CPT + cc];
    #pragma unroll
    for (int q = 0; q < T; ++q) { re[q] = pe[q * CPT]; rl[q] = pl[q * CPT]; }
    #pragma unroll
    for (int dp = 0; dp < T; ++dp) {             // round 13s + dp
        #pragma unroll
        for (int p = 0; 2 * p < dp; ++p) rot(re[p], re[dp - p], csE[p * T + (dp - p)]);
        if ((dp & 1) == 0) rot(re[dp >> 1], sp, csE[(dp >> 1) * T + (dp >> 1)]);
        if (dp <= T - 2) {
            const int dd = dp + T;
            #pragma unroll
            for (int p = dp + 1; 2 * p < dd; ++p) rot(rl[p], rl[dd - p], csL[p * T + (dd - p)]);
            if ((dd & 1) == 0) rot(rl[dd >> 1], sp, csL[(dd >> 1) * T + (dd >> 1)]);
        }
    }
    #pragma unroll
    for (int q = 0; q < T; ++q) { pe[q * CPT] = re[q]; pl[q * CPT] = rl[q]; }
    sm[MM * CPT + cc] = sp;
}

__global__ void __launch_bounds__(THREADS, 2)
rotmat_kernel(float* __restrict__ out) {
    extern __shared__ float sm[];                 // [4096 u-rows][7 cols]
    const int c0   = blockIdx.x * CPT;
    const int cols = min(4096 - c0, CPT);
    const int tid  = threadIdx.x;
    const int slot = tid / CPT;
    const int cc   = tid - slot * CPT;

    for (int i = tid; i < 4096 * CPT; i += THREADS) sm[i] = 0.0f;
    __syncthreads();
    if (tid < cols) {                             // identity in u-coordinates
        int c = c0 + tid;
        int u = (c == MM) ? MM : (int)((2048LL * c) % MM);
        sm[u * CPT + tid] = 1.0f;
    }
    __syncthreads();

    // Prologue: late halves of anti-diag 314 (rounds 0..11)
    if (slot < SLOTS)
        for (int m = 1 + slot; m <= NTILE; m += SLOTS) {
            int A, B; tileAB(NT - 1, m, A, B);
            visit<T, 24>(sm, A, B, cc, g_csF + ((size_t)(NT - 1) * 169) * NTILE + (m - 1));
        }
    __syncthreads();

    for (int s = 0; s < NT; ++s) {
        if (tid < CPT) {
            int aE = (s * 158) % NT;
            int aL = aE - 158; if (aL < 0) aL += NT;
            visit_diag(sm, aE, aL, tid);
        }
        __syncthreads();
        if (slot < SLOTS) {
            if (s < NT - 1) {
                for (int m = 1 + slot; m <= NTILE; m += SLOTS) {
                    int A, B; tileAB(s, m, A, B);
                    visit<0, 24>(sm, A, B, cc, g_csF + ((size_t)s * 169) * NTILE + (m - 1));
                }
            } else {   // epilogue: early halves of anti-diag 314 (rounds 4082..4094)
                for (int m = 1 + slot; m <= NTILE; m += SLOTS) {
                    int A, B; tileAB(NT - 1, m, A, B);
                    visit<0, 12>(sm, A, B, cc, g_csF + ((size_t)(NT - 1) * 169) * NTILE + (m - 1));
                }
            }
        }
        __syncthreads();
    }

    // Writeback: slab u-row v -> absolute row x = 2v mod 4095 (4095 -> 4095)
    for (int v = tid; v < 4096; v += THREADS) {
        int x = (v == MM) ? MM : ((2 * v) % MM);
        const float* src = sm + v * CPT;
        float* dst = out + (size_t)x * 4096 + c0;
        #pragma unroll
        for (int k = 0; k < CPT; ++k) if (k < cols) dst[k] = src[k];
    }
}

extern "C" void kernel_launch(void* const* d_in, const int* in_sizes, int n_in,
                              void* d_out, int out_size) {
    const float* thetas      = (const float*)d_in[0];
    const int*   round_theta = (const int*)d_in[3];
    float*       out         = (float*)d_out;
    (void)in_sizes; (void)n_in; (void)out_size;

    const int smem = 4096 * CPT * (int)sizeof(float);   // 114,688 B
    cudaFuncSetAttribute(rotmat_kernel,
                         cudaFuncAttributeMaxDynamicSharedMemorySize, smem);

    precompute<<<(int)((NPAIRS + 255) / 256), 256>>>(thetas, round_theta);

    const int nblocks = (4096 + CPT - 1) / CPT;         // 586
    rotmat_kernel<<<nblocks, THREADS, smem>>>(out);
}